// round 6
// baseline (speedup 1.0000x reference)
#include <cuda_runtime.h>

#define NN 100000
#define EE 1600000
#define PP 200000

// Scratch (allocation-free rule: __device__ globals)
__device__ float g_h0[NN * 64];   // 2x + scatter_sum
__device__ float g_h [NN * 64];   // node embedding after MLP
__device__ float g_u [NN * 64];   // h @ (A+C)
__device__ float g_v [NN * 64];   // h @ (A+D)
__device__ float g_AC[64 * 64];
__device__ float g_AD[64 * 64];

// ---------------------------------------------------------------------------
// K0: h0 = 2*x  (vectorized)
__global__ void k_init(const float* __restrict__ x) {
    int i = blockIdx.x * blockDim.x + threadIdx.x;
    if (i < NN * 16) {
        float4 v = reinterpret_cast<const float4*>(x)[i];
        v.x += v.x; v.y += v.y; v.z += v.z; v.w += v.w;
        reinterpret_cast<float4*>(g_h0)[i] = v;
    }
}

// ---------------------------------------------------------------------------
// K1: scatter  h0[dst] += x[src]  via 16B vector reductions (no return value)
__global__ void k_scatter(const float* __restrict__ x, const int* __restrict__ ei) {
    int u = blockIdx.x * blockDim.x + threadIdx.x;
    if (u >= EE * 16) return;
    int e = u >> 4;        // edge id
    int c = u & 15;        // float4 chunk within the 64-float feature
    int src = ei[e];
    int dst = ei[EE + e];
    float4 val = reinterpret_cast<const float4*>(x)[src * 16 + c];
    float* p = &g_h0[dst * 64 + c * 4];
    asm volatile("red.global.add.v4.f32 [%0], {%1, %2, %3, %4};"
                 :: "l"(p), "f"(val.x), "f"(val.y), "f"(val.z), "f"(val.w)
                 : "memory");
}

// ---------------------------------------------------------------------------
// K2: AC = A + C, AD = A + D  (dw1 = [A;B;C;D], each 64x64, row-major [k][f])
__global__ void k_prep(const float* __restrict__ dw1) {
    int i = blockIdx.x * blockDim.x + threadIdx.x;
    if (i < 4096) {
        float a = dw1[i];                      // A block: rows 0..63
        g_AC[i] = a + dw1[128 * 64 + i];       // + C block (rows 128..191)
        g_AD[i] = a + dw1[192 * 64 + i];       // + D block (rows 192..255)
    }
}

// ---------------------------------------------------------------------------
// K3: node MLP: h = relu( relu(h0@w1 + b1) @ w2 + b2 )
// One warp per node; lane l owns output features l and l+32.
__global__ void __launch_bounds__(256) k_mlp(
    const float* __restrict__ w1, const float* __restrict__ b1,
    const float* __restrict__ w2, const float* __restrict__ b2)
{
    __shared__ float  sw1[64 * 64];
    __shared__ float  sw2[64 * 64];
    __shared__ float4 stage[8][16];
    int tid = threadIdx.x;
    for (int i = tid; i < 4096; i += 256) { sw1[i] = w1[i]; sw2[i] = w2[i]; }
    __syncthreads();

    int wid  = tid >> 5;
    int lane = tid & 31;
    int node = blockIdx.x * 8 + wid;
    if (node >= NN) return;

    float* st = reinterpret_cast<float*>(stage[wid]);
    const float* h0 = g_h0 + node * 64;
    st[lane]      = h0[lane];
    st[lane + 32] = h0[lane + 32];
    __syncwarp();

    float acc0 = b1[lane], acc1 = b1[lane + 32];
    #pragma unroll
    for (int k4 = 0; k4 < 16; k4++) {
        float4 m = stage[wid][k4];
        int k = k4 * 4;
        acc0 += m.x * sw1[(k    ) * 64 + lane]; acc1 += m.x * sw1[(k    ) * 64 + lane + 32];
        acc0 += m.y * sw1[(k + 1) * 64 + lane]; acc1 += m.y * sw1[(k + 1) * 64 + lane + 32];
        acc0 += m.z * sw1[(k + 2) * 64 + lane]; acc1 += m.z * sw1[(k + 2) * 64 + lane + 32];
        acc0 += m.w * sw1[(k + 3) * 64 + lane]; acc1 += m.w * sw1[(k + 3) * 64 + lane + 32];
    }
    acc0 = fmaxf(acc0, 0.0f); acc1 = fmaxf(acc1, 0.0f);

    __syncwarp();
    st[lane] = acc0; st[lane + 32] = acc1;
    __syncwarp();

    acc0 = b2[lane]; acc1 = b2[lane + 32];
    #pragma unroll
    for (int k4 = 0; k4 < 16; k4++) {
        float4 m = stage[wid][k4];
        int k = k4 * 4;
        acc0 += m.x * sw2[(k    ) * 64 + lane]; acc1 += m.x * sw2[(k    ) * 64 + lane + 32];
        acc0 += m.y * sw2[(k + 1) * 64 + lane]; acc1 += m.y * sw2[(k + 1) * 64 + lane + 32];
        acc0 += m.z * sw2[(k + 2) * 64 + lane]; acc1 += m.z * sw2[(k + 2) * 64 + lane + 32];
        acc0 += m.w * sw2[(k + 3) * 64 + lane]; acc1 += m.w * sw2[(k + 3) * 64 + lane + 32];
    }
    acc0 = fmaxf(acc0, 0.0f); acc1 = fmaxf(acc1, 0.0f);
    g_h[node * 64 + lane]      = acc0;
    g_h[node * 64 + lane + 32] = acc1;
}

// ---------------------------------------------------------------------------
// K4: u = h @ AC, v = h @ AD   (one warp per node, both GEMVs fused)
__global__ void __launch_bounds__(256) k_uv() {
    __shared__ float  sAC[64 * 64];
    __shared__ float  sAD[64 * 64];
    __shared__ float4 stage[8][16];
    int tid = threadIdx.x;
    for (int i = tid; i < 4096; i += 256) { sAC[i] = g_AC[i]; sAD[i] = g_AD[i]; }
    __syncthreads();

    int wid  = tid >> 5;
    int lane = tid & 31;
    int node = blockIdx.x * 8 + wid;
    if (node >= NN) return;

    float* st = reinterpret_cast<float*>(stage[wid]);
    const float* h = g_h + node * 64;
    st[lane]      = h[lane];
    st[lane + 32] = h[lane + 32];
    __syncwarp();

    float u0 = 0.f, u1 = 0.f, v0 = 0.f, v1 = 0.f;
    #pragma unroll
    for (int k4 = 0; k4 < 16; k4++) {
        float4 m = stage[wid][k4];
        int k = k4 * 4;
        u0 += m.x * sAC[(k    ) * 64 + lane]; u1 += m.x * sAC[(k    ) * 64 + lane + 32];
        v0 += m.x * sAD[(k    ) * 64 + lane]; v1 += m.x * sAD[(k    ) * 64 + lane + 32];
        u0 += m.y * sAC[(k + 1) * 64 + lane]; u1 += m.y * sAC[(k + 1) * 64 + lane + 32];
        v0 += m.y * sAD[(k + 1) * 64 + lane]; v1 += m.y * sAD[(k + 1) * 64 + lane + 32];
        u0 += m.z * sAC[(k + 2) * 64 + lane]; u1 += m.z * sAC[(k + 2) * 64 + lane + 32];
        v0 += m.z * sAD[(k + 2) * 64 + lane]; v1 += m.z * sAD[(k + 2) * 64 + lane + 32];
        u0 += m.w * sAC[(k + 3) * 64 + lane]; u1 += m.w * sAC[(k + 3) * 64 + lane + 32];
        v0 += m.w * sAD[(k + 3) * 64 + lane]; v1 += m.w * sAD[(k + 3) * 64 + lane + 32];
    }
    g_u[node * 64 + lane]      = u0;
    g_u[node * 64 + lane + 32] = u1;
    g_v[node * 64 + lane]      = v0;
    g_v[node * 64 + lane + 32] = v1;
}

// ---------------------------------------------------------------------------
// K5: per pair p = (i,j):
//   z = relu( u[i] + v[j] + db1 + (h[i] (*) h[j]) @ B )
//   out[p] = z @ dw2 + db2
__global__ void __launch_bounds__(256) k_pair(
    const int* __restrict__ idx,
    const float* __restrict__ dw1, const float* __restrict__ db1,
    const float* __restrict__ dw2, const float* __restrict__ db2,
    float* __restrict__ out)
{
    __shared__ float  sB[64 * 64];
    __shared__ float  sdw2[64];
    __shared__ float4 stage[8][16];
    int tid = threadIdx.x;
    for (int i = tid; i < 4096; i += 256) sB[i] = dw1[64 * 64 + i];  // B block
    if (tid < 64) sdw2[tid] = dw2[tid];
    __syncthreads();

    int wid  = tid >> 5;
    int lane = tid & 31;
    int p = blockIdx.x * 8 + wid;
    if (p >= PP) return;

    int i = idx[p];
    int j = idx[PP + p];
    const float* e1 = g_h + i * 64;
    const float* e2 = g_h + j * 64;

    float* st = reinterpret_cast<float*>(stage[wid]);
    st[lane]      = e1[lane]      * e2[lane];
    st[lane + 32] = e1[lane + 32] * e2[lane + 32];
    __syncwarp();

    float acc0 = g_u[i * 64 + lane]      + g_v[j * 64 + lane]      + db1[lane];
    float acc1 = g_u[i * 64 + lane + 32] + g_v[j * 64 + lane + 32] + db1[lane + 32];
    #pragma unroll
    for (int k4 = 0; k4 < 16; k4++) {
        float4 m = stage[wid][k4];
        int k = k4 * 4;
        acc0 += m.x * sB[(k    ) * 64 + lane]; acc1 += m.x * sB[(k    ) * 64 + lane + 32];
        acc0 += m.y * sB[(k + 1) * 64 + lane]; acc1 += m.y * sB[(k + 1) * 64 + lane + 32];
        acc0 += m.z * sB[(k + 2) * 64 + lane]; acc1 += m.z * sB[(k + 2) * 64 + lane + 32];
        acc0 += m.w * sB[(k + 3) * 64 + lane]; acc1 += m.w * sB[(k + 3) * 64 + lane + 32];
    }
    acc0 = fmaxf(acc0, 0.0f); acc1 = fmaxf(acc1, 0.0f);

    float r = acc0 * sdw2[lane] + acc1 * sdw2[lane + 32];
    #pragma unroll
    for (int o = 16; o > 0; o >>= 1)
        r += __shfl_down_sync(0xffffffffu, r, o);
    if (lane == 0) out[p] = r + db2[0];
}

// ---------------------------------------------------------------------------
extern "C" void kernel_launch(void* const* d_in, const int* in_sizes, int n_in,
                              void* d_out, int out_size) {
    const float* x   = (const float*)d_in[0];
    const int*   ei  = (const int*)  d_in[1];
    // d_in[2] = curvature (unused by the output)
    const int*   idx = (const int*)  d_in[3];
    const float* w1  = (const float*)d_in[4];
    const float* b1  = (const float*)d_in[5];
    const float* w2  = (const float*)d_in[6];
    const float* b2  = (const float*)d_in[7];
    const float* dw1 = (const float*)d_in[8];
    const float* db1 = (const float*)d_in[9];
    const float* dw2 = (const float*)d_in[10];
    const float* db2 = (const float*)d_in[11];
    float* out = (float*)d_out;

    k_init   <<<(NN * 16 + 255) / 256, 256>>>(x);
    k_scatter<<<(EE * 16 + 255) / 256, 256>>>(x, ei);
    k_prep   <<<16, 256>>>(dw1);
    k_mlp    <<<(NN + 7) / 8, 256>>>(w1, b1, w2, b2);
    k_uv     <<<(NN + 7) / 8, 256>>>();
    k_pair   <<<(PP + 7) / 8, 256>>>(idx, dw1, db1, dw2, db2, out);
}